// round 1
// baseline (speedup 1.0000x reference)
#include <cuda_runtime.h>
#include <cstdint>

#define RB 16
#define NC 80
#define NB 16
#define NA 8400
#define CHN 144
#define KP 1024
#define MAXDET 300
#define CONF 0.25f
#define IOUT 0.45f

// ---------------- scratch (no allocations allowed) ----------------
__device__ float4 g_boxes[NB * NA];
__device__ float  g_score[NB * NA];
__device__ int    g_label[NB * NA];
__device__ unsigned long long g_keys[NB * NA];
__device__ unsigned long long g_mA[NB * 8 * 1024];
__device__ unsigned long long g_mB[NB * 8 * 1024];

__device__ __forceinline__ int read_dim(const int* p) {
    if (!p) return 640;
    int v = *p;
    if (v > 0 && v < 100000) return v;          // plausible int32
    float f = __int_as_float(v);                // maybe passed as float bits
    return (int)f;
}

// ---------------- Phase A: decode (DFL + sigmoid/argmax) ----------------
__global__ void decode_k(const float* __restrict__ p0, const float* __restrict__ p1,
                         const float* __restrict__ p2, const int* pH, const int* pW) {
    int gid = blockIdx.x * blockDim.x + threadIdx.x;
    if (gid >= NB * NA) return;
    int b = gid / NA, a = gid % NA;

    const float* p; int H, W, stride, lb;
    if (a < 6400)      { p = p0; H = 80; W = 80; stride = 8;  lb = 0;    }
    else if (a < 8000) { p = p1; H = 40; W = 40; stride = 16; lb = 6400; }
    else               { p = p2; H = 20; W = 20; stride = 32; lb = 8000; }
    int hw = a - lb, HW = H * W;
    int x = hw % W, y = hw / W;
    const float* base = p + ((size_t)b * CHN) * HW + hw;

    // DFL: softmax over 16 bins per side, expectation * stride
    float d[4];
    #pragma unroll
    for (int k = 0; k < 4; k++) {
        float v[RB]; float mx = -1e30f;
        #pragma unroll
        for (int r = 0; r < RB; r++) {
            v[r] = base[(size_t)(k * RB + r) * HW];
            mx = fmaxf(mx, v[r]);
        }
        float s = 0.f, ws = 0.f;
        #pragma unroll
        for (int r = 0; r < RB; r++) {
            float e = expf(v[r] - mx);
            s += e; ws += e * (float)r;
        }
        d[k] = ws / s * (float)stride;
    }
    float cx = ((float)x + 0.5f) * (float)stride;
    float cy = ((float)y + 0.5f) * (float)stride;

    // class max + first-argmax (sigmoid monotone -> argmax over logits)
    float mx2 = -1e30f; int lbl = 0;
    #pragma unroll 4
    for (int c = 0; c < NC; c++) {
        float z = base[(size_t)(64 + c) * HW];
        if (z > mx2) { mx2 = z; lbl = c; }
    }
    float sc = 1.0f / (1.0f + expf(-mx2));

    int himg = read_dim(pH), wimg = read_dim(pW);
    float hiW = (float)(wimg - 1), hiH = (float)(himg - 1);
    float x1 = fminf(fmaxf(cx - d[0], 0.f), hiW);
    float y1 = fminf(fmaxf(cy - d[1], 0.f), hiH);
    float x2 = fminf(fmaxf(cx + d[2], 0.f), hiW);
    float y2 = fminf(fmaxf(cy + d[3], 0.f), hiH);

    g_boxes[gid] = make_float4(x1, y1, x2, y2);
    g_label[gid] = lbl;
    float sp = (sc > CONF) ? sc : -1.0f;     // reference's conf mask before top_k
    g_score[gid] = sp;

    // sortable key: ascending key == (score desc, anchor asc)  [matches lax.top_k ties]
    unsigned u = __float_as_uint(sp);
    u = (u & 0x80000000u) ? ~u : (u | 0x80000000u);   // monotone float->uint
    unsigned hi32 = ~u;                                // invert: larger score -> smaller key
    g_keys[gid] = ((unsigned long long)hi32 << 32) | (unsigned)a;
}

// ---------------- Phase B1: per-chunk bitonic sort (8 chunks x 16 batches) ----------------
__global__ __launch_bounds__(1024) void sort_chunk_k() {
    __shared__ unsigned long long s[2048];
    int b = blockIdx.x >> 3, c = blockIdx.x & 7;
    int base = c * 1050;                                 // 8*1050 = 8400
    for (int i = threadIdx.x; i < 2048; i += 1024) {
        int a = base + i;
        s[i] = (i < 1050 && a < NA) ? g_keys[b * NA + a] : 0xFFFFFFFFFFFFFFFFull;
    }
    __syncthreads();
    for (int k = 2; k <= 2048; k <<= 1)
        for (int j = k >> 1; j > 0; j >>= 1) {
            for (int i = threadIdx.x; i < 2048; i += 1024) {
                int ixj = i ^ j;
                if (ixj > i) {
                    bool asc = ((i & k) == 0);
                    unsigned long long av = s[i], bv = s[ixj];
                    if ((av > bv) == asc) { s[i] = bv; s[ixj] = av; }
                }
            }
            __syncthreads();
        }
    g_mA[(size_t)(b * 8 + c) * 1024 + threadIdx.x] = s[threadIdx.x];  // lowest 1024, sorted asc
}

// ---------------- Phase B2: tournament merge keeping lowest 1024 ----------------
__global__ __launch_bounds__(1024) void merge_k(int round) {
    const unsigned long long* in; unsigned long long* out; int npairs;
    if (round == 0)      { in = g_mA; out = g_mB; npairs = 4; }
    else if (round == 1) { in = g_mB; out = g_mA; npairs = 2; }
    else                 { in = g_mA; out = g_mB; npairs = 1; }

    __shared__ unsigned long long s[2048];
    int b = blockIdx.x / npairs, p = blockIdx.x % npairs;
    const unsigned long long* A  = in + ((size_t)b * 8 + 2 * p) * 1024;
    const unsigned long long* Bl = A + 1024;
    s[threadIdx.x]        = A[threadIdx.x];
    s[2047 - threadIdx.x] = Bl[threadIdx.x];   // reversed -> bitonic 2048
    __syncthreads();
    for (int j = 1024; j > 0; j >>= 1) {
        for (int i = threadIdx.x; i < 2048; i += 1024) {
            int ixj = i ^ j;
            if (ixj > i) {
                unsigned long long av = s[i], bv = s[ixj];
                if (av > bv) { s[i] = bv; s[ixj] = av; }
            }
        }
        __syncthreads();
    }
    out[((size_t)b * 8 + p) * 1024 + threadIdx.x] = s[threadIdx.x];
}

// ---------------- Phase C: per-class greedy NMS + output ----------------
__global__ __launch_bounds__(1024) void nms_k(float* __restrict__ out) {
    __shared__ float4 sbox[KP];
    __shared__ float  ssc[KP];
    __shared__ short  slab[KP];
    __shared__ unsigned char skeep[KP];
    __shared__ int wsum[33];

    int b = blockIdx.x, tid = threadIdx.x, w = tid >> 5, lane = tid & 31;
    unsigned long long key = g_mB[(size_t)b * 8192 + tid];   // final merged list at slot 0
    unsigned a = (unsigned)(key & 0xFFFFFFFFu);
    int g = b * NA + (int)a;
    sbox[tid] = g_boxes[g];
    ssc[tid]  = g_score[g];
    slab[tid] = (short)g_label[g];
    skeep[tid] = 0;
    __syncthreads();

    // cross-class IoU is exactly 0 (offset 4096 > coords) -> 80 independent chains
    for (int c = w; c < NC; c += 32) {
        float4 kept[4];                 // up to 128 kept/class, lane-distributed (>>30 sigma margin)
        int nk = 0;
        float off = (float)c * 4096.0f;
        for (int bk = 0; bk < KP; bk += 32) {
            int k2 = bk + lane;
            bool m = (slab[k2] == c) && (ssc[k2] > CONF);
            unsigned mm = __ballot_sync(0xFFFFFFFFu, m);
            while (mm) {
                int kk = bk + (__ffs(mm) - 1); mm &= mm - 1;   // next candidate in rank order
                float4 bx = sbox[kk];
                // offset boxes, non-fused ops -> match reference rounding at the threshold
                float x1 = __fadd_rn(bx.x, off), y1 = __fadd_rn(bx.y, off);
                float x2 = __fadd_rn(bx.z, off), y2 = __fadd_rn(bx.w, off);
                float areaC = __fmul_rn(__fsub_rn(x2, x1), __fsub_rn(y2, y1));
                bool sup = false;
                #pragma unroll
                for (int s2 = 0; s2 < 4; s2++) {
                    if (s2 * 32 + lane < nk) {
                        float4 kb = kept[s2];
                        float lx = fmaxf(x1, kb.x), ly = fmaxf(y1, kb.y);
                        float rx = fminf(x2, kb.z), ry = fminf(y2, kb.w);
                        float iw = fmaxf(__fsub_rn(rx, lx), 0.f);
                        float ih = fmaxf(__fsub_rn(ry, ly), 0.f);
                        float inter = __fmul_rn(iw, ih);
                        float areaK = __fmul_rn(__fsub_rn(kb.z, kb.x), __fsub_rn(kb.w, kb.y));
                        float den = __fadd_rn(__fsub_rn(__fadd_rn(areaK, areaC), inter), 1e-7f);
                        if (__fdiv_rn(inter, den) > IOUT) sup = true;
                    }
                }
                if (__ballot_sync(0xFFFFFFFFu, sup) == 0u) {
                    int slot = nk >> 5;
                    if (lane == (nk & 31)) {
                        float4 nb = make_float4(x1, y1, x2, y2);
                        if (slot == 0) kept[0] = nb;
                        else if (slot == 1) kept[1] = nb;
                        else if (slot == 2) kept[2] = nb;
                        else if (slot == 3) kept[3] = nb;
                    }
                    if (lane == 0) skeep[kk] = 1;
                    nk++;
                }
            }
        }
    }
    __syncthreads();

    // rank = exclusive prefix of keep flags in score order
    int kv = skeep[tid];
    unsigned bal = __ballot_sync(0xFFFFFFFFu, kv != 0);
    int wpre = __popc(bal & ((1u << lane) - 1u));
    if (lane == 0) wsum[w] = __popc(bal);
    __syncthreads();
    if (w == 0) {
        int v = wsum[lane], orig = v;
        #pragma unroll
        for (int o = 1; o < 32; o <<= 1) {
            int t = __shfl_up_sync(0xFFFFFFFFu, v, o);
            if (lane >= o) v += t;
        }
        wsum[lane] = v - orig;
        if (lane == 31) wsum[32] = v;
    }
    __syncthreads();
    int n = min(wsum[32], MAXDET);

    // output layout guess: boxes(16,300,4) | scores(16,300) | labels(16,300) | valid(16,300), all f32
    const int OB = 0;
    const int OS = NB * MAXDET * 4;
    const int OL = OS + NB * MAXDET;
    const int OV = OL + NB * MAXDET;

    if (kv) {
        int rk = wsum[w] + wpre;
        if (rk < MAXDET) {
            float4 bx = sbox[tid];
            float* ob = out + OB + ((size_t)b * MAXDET + rk) * 4;
            ob[0] = bx.x; ob[1] = bx.y; ob[2] = bx.z; ob[3] = bx.w;
            out[OS + b * MAXDET + rk] = ssc[tid];
            out[OL + b * MAXDET + rk] = (float)slab[tid];
        }
    }
    if (tid < MAXDET) {
        if (tid >= n) {
            float* ob = out + OB + ((size_t)b * MAXDET + tid) * 4;
            ob[0] = 0.f; ob[1] = 0.f; ob[2] = 0.f; ob[3] = 0.f;
            out[OS + b * MAXDET + tid] = 0.f;
            out[OL + b * MAXDET + tid] = -1.f;
        }
        out[OV + b * MAXDET + tid] = (tid < n) ? 1.f : 0.f;
    }
}

// ---------------- launch ----------------
extern "C" void kernel_launch(void* const* d_in, const int* in_sizes, int n_in,
                              void* d_out, int out_size) {
    (void)in_sizes; (void)out_size;
    const float* p0 = (const float*)d_in[0];
    const float* p1 = (const float*)d_in[1];
    const float* p2 = (const float*)d_in[2];
    const int* pH = (n_in > 3) ? (const int*)d_in[3] : nullptr;
    const int* pW = (n_in > 4) ? (const int*)d_in[4] : nullptr;

    int total = NB * NA;
    decode_k<<<(total + 255) / 256, 256>>>(p0, p1, p2, pH, pW);
    sort_chunk_k<<<NB * 8, 1024>>>();
    merge_k<<<NB * 4, 1024>>>(0);
    merge_k<<<NB * 2, 1024>>>(1);
    merge_k<<<NB * 1, 1024>>>(2);
    nms_k<<<NB, 1024>>>((float*)d_out);
}

// round 2
// speedup vs baseline: 1.3413x; 1.3413x over previous
#include <cuda_runtime.h>
#include <cstdint>

#define RB 16
#define NC 80
#define NB 16
#define NA 8400
#define CHN 144
#define KP 1024
#define MAXDET 300
#define CONF 0.25f
#define IOUT 0.45f

// ---------------- scratch (no allocations allowed) ----------------
__device__ float4 g_boxes[NB * NA];
__device__ float  g_score[NB * NA];
__device__ int    g_label[NB * NA];
__device__ unsigned long long g_keys[NB * NA];

__device__ __forceinline__ int read_dim(const int* p) {
    if (!p) return 640;
    int v = *p;
    if (v > 0 && v < 100000) return v;
    float f = __int_as_float(v);
    return (int)f;
}

// ---------------- Phase A: decode (DFL + sigmoid/argmax), 2 anchors/thread --------
__global__ __launch_bounds__(128) void decode_k(const float* __restrict__ p0,
                                                const float* __restrict__ p1,
                                                const float* __restrict__ p2,
                                                const int* pH, const int* pW) {
    int gid = blockIdx.x * blockDim.x + threadIdx.x;
    const int tot = NB * NA / 2;
    if (gid >= tot) return;
    int b = gid / (NA / 2);
    int a2 = (gid - b * (NA / 2)) * 2;

    const float* p; int W, stride, lb, HW;
    if (a2 < 6400)      { p = p0; W = 80; stride = 8;  lb = 0;    HW = 6400; }
    else if (a2 < 8000) { p = p1; W = 40; stride = 16; lb = 6400; HW = 1600; }
    else                { p = p2; W = 20; stride = 32; lb = 8000; HW = 400;  }
    int hw = a2 - lb;
    int HW2 = HW >> 1;
    const float2* base = (const float2*)(p + (size_t)b * CHN * HW) + (hw >> 1);

    // DFL: per side, softmax over 16 bins (max-subtracted, same op order as the
    // validated round-1 kernel), expectation * stride.
    float2 dd[4];
    #pragma unroll
    for (int k = 0; k < 4; k++) {
        float2 v[RB];
        #pragma unroll
        for (int r = 0; r < RB; r++) v[r] = base[(size_t)(k * RB + r) * HW2];
        float mxx = -1e30f, mxy = -1e30f;
        #pragma unroll
        for (int r = 0; r < RB; r++) { mxx = fmaxf(mxx, v[r].x); mxy = fmaxf(mxy, v[r].y); }
        float sx = 0.f, wsx = 0.f, sy = 0.f, wsy = 0.f;
        #pragma unroll
        for (int r = 0; r < RB; r++) {
            float fr = (float)r;
            float ex = expf(v[r].x - mxx); sx += ex; wsx += ex * fr;
            float ey = expf(v[r].y - mxy); sy += ey; wsy += ey * fr;
        }
        dd[k].x = wsx / sx * (float)stride;
        dd[k].y = wsy / sy * (float)stride;
    }

    // class max + first-argmax (strict >, first wins — matches reference argmax)
    float2 mx2 = base[(size_t)64 * HW2];
    int lx = 0, ly = 0;
    #pragma unroll 8
    for (int c = 1; c < NC; c++) {
        float2 z = base[(size_t)(64 + c) * HW2];
        if (z.x > mx2.x) { mx2.x = z.x; lx = c; }
        if (z.y > mx2.y) { mx2.y = z.y; ly = c; }
    }

    int himg = read_dim(pH), wimg = read_dim(pW);
    float hiW = (float)(wimg - 1), hiH = (float)(himg - 1);
    float st = (float)stride;
    int y0 = hw / W, x0 = hw % W;              // hw even, W even -> same row
    float cy = ((float)y0 + 0.5f) * st;

    #pragma unroll
    for (int j = 0; j < 2; j++) {
        float dl = j ? dd[0].y : dd[0].x;
        float dt = j ? dd[1].y : dd[1].x;
        float dr = j ? dd[2].y : dd[2].x;
        float db = j ? dd[3].y : dd[3].x;
        float mxc = j ? mx2.y : mx2.x;
        int   lbl = j ? ly : lx;
        float cx = ((float)(x0 + j) + 0.5f) * st;
        float x1 = fminf(fmaxf(cx - dl, 0.f), hiW);
        float y1 = fminf(fmaxf(cy - dt, 0.f), hiH);
        float x2 = fminf(fmaxf(cx + dr, 0.f), hiW);
        float y2 = fminf(fmaxf(cy + db, 0.f), hiH);
        int g = b * NA + a2 + j;
        g_boxes[g] = make_float4(x1, y1, x2, y2);
        g_label[g] = lbl;
        float sc = 1.0f / (1.0f + expf(-mxc));
        float sp = (sc > CONF) ? sc : -1.0f;
        g_score[g] = sp;
        unsigned u = __float_as_uint(sp);
        u = (u & 0x80000000u) ? ~u : (u | 0x80000000u);
        g_keys[g] = ((unsigned long long)(~u) << 32) | (unsigned)(a2 + j);
    }
}

// ---------------- Phase B: fused radix-select top-1024 + sort + NMS + output -------
__global__ __launch_bounds__(1024) void topk_nms_k(float* __restrict__ out) {
    __shared__ unsigned long long gath[KP];     // 8KB
    __shared__ unsigned int hist[2048];         // 8KB
    __shared__ float4 sbox[KP];                 // 16KB
    __shared__ float  ssc[KP];                  // 4KB
    __shared__ short  slab[KP];                 // 2KB
    __shared__ unsigned char skeep[KP];         // 1KB
    __shared__ int wsum[33];
    __shared__ unsigned int wtot[32];
    __shared__ unsigned long long s_kth;
    __shared__ int s_b, s_rank, s_cnt, s_gcnt;

    int b = blockIdx.x, tid = threadIdx.x, w = tid >> 5, lane = tid & 31;
    const unsigned long long* keys = g_keys + (size_t)b * NA;

    // --- exact radix select of the 1024th-smallest 64-bit key (keys are unique:
    // low bits are the anchor index) ---
    unsigned long long prefix = 0, pmask = 0, kth;
    int rank = KP;
    bool found = false;
    const int shifts[6] = {53, 42, 31, 20, 9, 0};
    #pragma unroll 1
    for (int pass = 0; pass < 6 && !found; pass++) {
        int sh = shifts[pass];
        unsigned bm = (pass == 5) ? 511u : 2047u;
        hist[tid] = 0; hist[tid + 1024] = 0;
        __syncthreads();
        for (int i = tid; i < NA; i += 1024) {
            unsigned long long k = keys[i];
            if ((k & pmask) == prefix)
                atomicAdd(&hist[(unsigned)(k >> sh) & bm], 1u);
        }
        __syncthreads();
        // inclusive scan over 2048 buckets (2 per thread)
        unsigned e0 = hist[2 * tid], e1 = hist[2 * tid + 1];
        unsigned incl = e0 + e1;
        #pragma unroll
        for (int o = 1; o < 32; o <<= 1) {
            unsigned t = __shfl_up_sync(0xFFFFFFFFu, incl, o);
            if (lane >= o) incl += t;
        }
        if (lane == 31) wtot[w] = incl;
        __syncthreads();
        if (w == 0) {
            unsigned v = wtot[lane], iv = v;
            #pragma unroll
            for (int o = 1; o < 32; o <<= 1) {
                unsigned t = __shfl_up_sync(0xFFFFFFFFu, iv, o);
                if (lane >= o) iv += t;
            }
            wtot[lane] = iv - v;                       // exclusive warp base
        }
        __syncthreads();
        unsigned incl1 = wtot[w] + incl;               // inclusive at bucket 2t+1
        unsigned incl0 = incl1 - e1;
        unsigned excl0 = incl0 - e0, excl1 = incl1 - e1;
        unsigned r_ = (unsigned)rank;
        if (e0 && excl0 < r_ && r_ <= incl0) { s_b = 2 * tid;     s_rank = (int)(r_ - excl0); s_cnt = (int)e0; }
        if (e1 && excl1 < r_ && r_ <= incl1) { s_b = 2 * tid + 1; s_rank = (int)(r_ - excl1); s_cnt = (int)e1; }
        __syncthreads();
        prefix |= ((unsigned long long)(unsigned)s_b) << sh;
        pmask  |= ((unsigned long long)bm) << sh;
        rank = s_rank;
        if (s_cnt == 1) {
            for (int i = tid; i < NA; i += 1024) {
                unsigned long long k = keys[i];
                if ((k & pmask) == prefix) s_kth = k;
            }
            found = true;
        }
        __syncthreads();
    }
    kth = found ? s_kth : prefix;

    // --- gather exactly 1024 keys <= kth, then bitonic sort ascending ---
    if (tid == 0) s_gcnt = 0;
    __syncthreads();
    for (int i = tid; i < NA; i += 1024) {
        unsigned long long k = keys[i];
        if (k <= kth) { int pI = atomicAdd(&s_gcnt, 1); gath[pI] = k; }
    }
    __syncthreads();
    for (int kk = 2; kk <= KP; kk <<= 1)
        for (int j = kk >> 1; j > 0; j >>= 1) {
            int i = tid, ixj = i ^ j;
            if (ixj > i && i < KP) {
                bool asc = ((i & kk) == 0);
                unsigned long long av = gath[i], bv = gath[ixj];
                if ((av > bv) == asc) { gath[i] = bv; gath[ixj] = av; }
            }
            __syncthreads();
        }

    // --- NMS (validated round-1 code; cross-class IoU is exactly 0 due to the
    // 4096 class offset -> 80 independent greedy chains, one warp per class) ---
    unsigned long long key = gath[tid];
    unsigned a = (unsigned)(key & 0xFFFFFFFFu);
    int g = b * NA + (int)a;
    sbox[tid] = g_boxes[g];
    ssc[tid]  = g_score[g];
    slab[tid] = (short)g_label[g];
    skeep[tid] = 0;
    __syncthreads();

    for (int c = w; c < NC; c += 32) {
        float4 kept[4];
        int nk = 0;
        float off = (float)c * 4096.0f;
        for (int bk = 0; bk < KP; bk += 32) {
            int k2 = bk + lane;
            bool m = (slab[k2] == c) && (ssc[k2] > CONF);
            unsigned mm = __ballot_sync(0xFFFFFFFFu, m);
            while (mm) {
                int kk2 = bk + (__ffs(mm) - 1); mm &= mm - 1;
                float4 bx = sbox[kk2];
                float x1 = __fadd_rn(bx.x, off), y1 = __fadd_rn(bx.y, off);
                float x2 = __fadd_rn(bx.z, off), y2 = __fadd_rn(bx.w, off);
                float areaC = __fmul_rn(__fsub_rn(x2, x1), __fsub_rn(y2, y1));
                bool sup = false;
                #pragma unroll
                for (int s2 = 0; s2 < 4; s2++) {
                    if (s2 * 32 + lane < nk) {
                        float4 kb = kept[s2];
                        float lx2 = fmaxf(x1, kb.x), ly2 = fmaxf(y1, kb.y);
                        float rx = fminf(x2, kb.z), ry = fminf(y2, kb.w);
                        float iw = fmaxf(__fsub_rn(rx, lx2), 0.f);
                        float ih = fmaxf(__fsub_rn(ry, ly2), 0.f);
                        float inter = __fmul_rn(iw, ih);
                        float areaK = __fmul_rn(__fsub_rn(kb.z, kb.x), __fsub_rn(kb.w, kb.y));
                        float den = __fadd_rn(__fsub_rn(__fadd_rn(areaK, areaC), inter), 1e-7f);
                        if (__fdiv_rn(inter, den) > IOUT) sup = true;
                    }
                }
                if (__ballot_sync(0xFFFFFFFFu, sup) == 0u) {
                    int slot = nk >> 5;
                    if (lane == (nk & 31)) {
                        float4 nb = make_float4(x1, y1, x2, y2);
                        if (slot == 0) kept[0] = nb;
                        else if (slot == 1) kept[1] = nb;
                        else if (slot == 2) kept[2] = nb;
                        else kept[3] = nb;
                    }
                    if (lane == 0) skeep[kk2] = 1;
                    nk++;
                }
            }
        }
    }
    __syncthreads();

    // rank = exclusive prefix of keep flags in score order
    int kv = skeep[tid];
    unsigned bal = __ballot_sync(0xFFFFFFFFu, kv != 0);
    int wpre = __popc(bal & ((1u << lane) - 1u));
    if (lane == 0) wsum[w] = __popc(bal);
    __syncthreads();
    if (w == 0) {
        int v = wsum[lane], orig = v;
        #pragma unroll
        for (int o = 1; o < 32; o <<= 1) {
            int t = __shfl_up_sync(0xFFFFFFFFu, v, o);
            if (lane >= o) v += t;
        }
        wsum[lane] = v - orig;
        if (lane == 31) wsum[32] = v;
    }
    __syncthreads();
    int n = min(wsum[32], MAXDET);

    const int OB = 0;
    const int OS = NB * MAXDET * 4;
    const int OL = OS + NB * MAXDET;
    const int OV = OL + NB * MAXDET;

    if (kv) {
        int rk = wsum[w] + wpre;
        if (rk < MAXDET) {
            float4 bx = sbox[tid];
            float* ob = out + OB + ((size_t)b * MAXDET + rk) * 4;
            ob[0] = bx.x; ob[1] = bx.y; ob[2] = bx.z; ob[3] = bx.w;
            out[OS + b * MAXDET + rk] = ssc[tid];
            out[OL + b * MAXDET + rk] = (float)slab[tid];
        }
    }
    if (tid < MAXDET) {
        if (tid >= n) {
            float* ob = out + OB + ((size_t)b * MAXDET + tid) * 4;
            ob[0] = 0.f; ob[1] = 0.f; ob[2] = 0.f; ob[3] = 0.f;
            out[OS + b * MAXDET + tid] = 0.f;
            out[OL + b * MAXDET + tid] = -1.f;
        }
        out[OV + b * MAXDET + tid] = (tid < n) ? 1.f : 0.f;
    }
}

// ---------------- launch ----------------
extern "C" void kernel_launch(void* const* d_in, const int* in_sizes, int n_in,
                              void* d_out, int out_size) {
    (void)in_sizes; (void)out_size;
    const float* p0 = (const float*)d_in[0];
    const float* p1 = (const float*)d_in[1];
    const float* p2 = (const float*)d_in[2];
    const int* pH = (n_in > 3) ? (const int*)d_in[3] : nullptr;
    const int* pW = (n_in > 4) ? (const int*)d_in[4] : nullptr;

    int tot = NB * NA / 2;
    decode_k<<<(tot + 127) / 128, 128>>>(p0, p1, p2, pH, pW);
    topk_nms_k<<<NB, 1024>>>((float*)d_out);
}